// round 10
// baseline (speedup 1.0000x reference)
#include <cuda_runtime.h>
#include <cstdint>

#define BB 8
#define NN 262144
#define KK 256
#define DD 16
#define CAP 2048
#define MMAX 1024
#define REP_BLOCKS 64          // rep j-chunk blocks per event
#define RCH 16                 // rep j-chunk size

// ---------------- scratch (device globals; zero == reset state) ----------------
__device__ float  g_sum_f [BB][KK];
__device__ int    g_cnt_cp[BB][KK];
__device__ int    g_inst  [BB][KK];
__device__ int    g_first [BB][KK];   // stores max(NN - li); 0 == no CP
__device__ float  g_sd2   [BB][KK];
__device__ float4 g_anchor[BB][KK][4];
__device__ int    g_Mv    [BB];
__device__ int    g_cplist[BB][CAP];
__device__ float  g_scal_f[BB][4];    // 0: sum ce0*~cp, 1: sum ce0*bg, 2: pos_margin, 3: neg_margin
__device__ int    g_scal_i[BB][2];    // 0: n_cp(all), 1: n_bg
__device__ float  g_rep   [BB];
__device__ float4 g_cpemb [BB][MMAX * 4];

// fast sigmoid + softplus: 2 MUFU + FMA-pipe Newton rcp (seed valid on u in (1,2])
__device__ __forceinline__ void fast_sig_sp(float x, float& p, float& ce0) {
    const float t = __expf(-fabsf(x));
    const float u = 1.f + t;
    float y = __fmaf_rn(u, -0.47058824f, 1.4117647f);
    y = y * __fmaf_rn(-u, y, 2.f);
    y = y * __fmaf_rn(-u, y, 2.f);
    ce0 = fmaxf(x, 0.f) + __logf(u);
    p   = (x >= 0.f) ? y : t * y;
}

// ---------------- pass A: full prefetch (12 LDG.128 in flight), grid 64x8 ----------
__global__ void __launch_bounds__(256) pass_a_kernel(
    const float* __restrict__ beta,
    const int* __restrict__ sid,
    const int* __restrict__ cp)
{
    const int b   = blockIdx.y;
    const int tid = threadIdx.x;

    __shared__ float s_f[KK];
    __shared__ int   s_cnt[KK];
    __shared__ int   s_first[KK];
    __shared__ float s_sc[4];
    __shared__ int   s_si[2];

    s_f[tid] = 0.f; s_cnt[tid] = 0; s_first[tid] = 0;
    if (tid < 4) s_sc[tid] = 0.f;
    if (tid < 2) s_si[tid] = 0;
    __syncthreads();

    float ce0n = 0.f, bg = 0.f, pm = 0.f, nm = 0.f;
    int ncp = 0, nbg = 0;

    const size_t ev_base = (size_t)b * NN;
    const int blk_base = blockIdx.x * 4096;

    int4 s4[4], c4[4];
    float4 x4[4];
    #pragma unroll
    for (int it = 0; it < 4; it++) {
        const int li0 = blk_base + it * 1024 + tid * 4;
        s4[it] = *reinterpret_cast<const int4*>(sid + ev_base + li0);
        c4[it] = *reinterpret_cast<const int4*>(cp  + ev_base + li0);
        x4[it] = *reinterpret_cast<const float4*>(beta + ev_base + li0);
    }

    #pragma unroll
    for (int it = 0; it < 4; it++) {
        const int li0 = blk_base + it * 1024 + tid * 4;
        const int   sv[4] = {s4[it].x, s4[it].y, s4[it].z, s4[it].w};
        const int   cv[4] = {c4[it].x, c4[it].y, c4[it].z, c4[it].w};
        const float xv[4] = {x4[it].x, x4[it].y, x4[it].z, x4[it].w};

        #pragma unroll
        for (int j = 0; j < 4; j++) {
            const int   s = sv[j];
            const float x = xv[j];
            float p, ce0;
            fast_sig_sp(x, p, ce0);

            if (cv[j]) {
                ncp++;
                pm += fmaxf(0.8f - p, 0.f);
                if (s >= 0) {
                    const float om = 1.f - p;
                    atomicAdd(&s_f[s], 0.75f * om * om * (ce0 - x));
                    atomicAdd(&s_cnt[s], 1);
                    atomicMax(&s_first[s], NN - (li0 + j));
                    int pos = atomicAdd(&g_Mv[b], 1);
                    if (pos < CAP) g_cplist[b][pos] = li0 + j;
                }
            } else {
                ce0n += ce0;
                nm += fmaxf(p - 0.2f, 0.f);
            }
            if (s == -1) { nbg++; bg += ce0; }
        }
    }

    atomicAdd(&s_sc[0], ce0n);
    atomicAdd(&s_sc[1], bg);
    atomicAdd(&s_sc[2], pm);
    atomicAdd(&s_sc[3], nm);
    atomicAdd(&s_si[0], ncp);
    atomicAdd(&s_si[1], nbg);
    __syncthreads();

    if (s_f[tid] != 0.f) atomicAdd(&g_sum_f[b][tid], s_f[tid]);
    if (s_cnt[tid])      atomicAdd(&g_cnt_cp[b][tid], s_cnt[tid]);
    if (s_first[tid])    atomicMax(&g_first[b][tid], s_first[tid]);
    if (tid < 4) atomicAdd(&g_scal_f[b][tid], s_sc[tid]);
    if (tid < 2) atomicAdd(&g_scal_i[b][tid], s_si[tid]);
}

// ---------------- rep prep (+ anchor gather): one block per event ----------------
__global__ void __launch_bounds__(1024) rep_prep_kernel(const float* __restrict__ embed) {
    const int b   = blockIdx.x;
    const int tid = threadIdx.x;
    __shared__ int sidx[CAP];

    for (int t = tid; t < KK * 4; t += 1024) {
        const int q = t & 3, k = t >> 2;
        const int val = g_first[b][k];
        float4 v = make_float4(0.f, 0.f, 0.f, 0.f);
        if (val > 0) {
            const int fi = NN - val;
            v = reinterpret_cast<const float4*>(embed + ((size_t)b * NN + fi) * DD)[q];
        }
        g_anchor[b][k][q] = v;
    }

    const int Mv   = g_Mv[b];
    const int mcol = min(Mv, CAP);
    const int msel = min(Mv, MMAX);

    for (int i = tid; i < CAP; i += 1024)
        sidx[i] = (i < mcol) ? g_cplist[b][i] : 0x7fffffff;
    __syncthreads();

    if (Mv > MMAX) {   // statistically never; correctness fallback
        for (int ksz = 2; ksz <= CAP; ksz <<= 1) {
            for (int j = ksz >> 1; j > 0; j >>= 1) {
                for (int i = tid; i < CAP; i += 1024) {
                    int ixj = i ^ j;
                    if (ixj > i) {
                        bool up = ((i & ksz) == 0);
                        int a = sidx[i], c = sidx[ixj];
                        if ((a > c) == up) { sidx[i] = c; sidx[ixj] = a; }
                    }
                }
                __syncthreads();
            }
        }
    }

    for (int t = tid; t < msel * 4; t += 1024) {
        const int i = t >> 2, qq = t & 3;
        g_cpemb[b][i * 4 + qq] =
            reinterpret_cast<const float4*>(embed + ((size_t)b * NN + sidx[i]) * DD)[qq];
    }
}

// ---------------- repulsion compute: grid (64 j-chunks, BB), 256 thr ----------------
__global__ void __launch_bounds__(256) rep_compute_kernel() {
    const int b   = blockIdx.y;
    const int tid = threadIdx.x;
    const int j0  = blockIdx.x * RCH;

    const int Mv   = g_Mv[b];
    const int msel = min(Mv, MMAX);
    if (j0 >= msel) return;                        // block-uniform
    const int cnt = min(RCH, msel - j0);

    __shared__ float sj[RCH * DD];                 // 1 KB
    __shared__ float red[8];

    for (int t = tid; t < cnt * 4; t += 256) {
        const int j = t >> 2, qq = t & 3;
        reinterpret_cast<float4*>(sj)[j * 4 + qq] = g_cpemb[b][(j0 + j) * 4 + qq];
    }
    __syncthreads();

    float acc = 0.f;
    for (int i = tid; i < msel; i += 256) {
        float myE[DD];
        #pragma unroll
        for (int qq = 0; qq < 4; qq++) {
            const float4 v = g_cpemb[b][i * 4 + qq];
            myE[qq * 4 + 0] = v.x; myE[qq * 4 + 1] = v.y;
            myE[qq * 4 + 2] = v.z; myE[qq * 4 + 3] = v.w;
        }
        #pragma unroll
        for (int j = 0; j < RCH; j++) {
            if (j < cnt) {
                float d2 = 0.f;
                #pragma unroll
                for (int d = 0; d < DD; d++) {
                    const float df = myE[d] - sj[j * DD + d];
                    d2 = __fmaf_rn(df, df, d2);
                }
                acc += __expf(-d2);
            }
        }
    }

    #pragma unroll
    for (int off = 16; off; off >>= 1) acc += __shfl_down_sync(0xffffffff, acc, off);
    if ((tid & 31) == 0) red[tid >> 5] = acc;
    __syncthreads();
    if (tid == 0) {
        float tot = 0.f;
        #pragma unroll
        for (int w = 0; w < 8; w++) tot += red[w];
        atomicAdd(&g_rep[b], tot);
    }
}

// ---------------- pass B: unconditional streaming, 4 lanes per row -----------------
// 256 thr, grid (128, BB). Warp covers 256 rows (8 rows/iter x 32 iters, unroll 8).
// Loads are UNCONDITIONAL (DRAM moves whole lines anyway); only accumulation is gated.
__global__ void __launch_bounds__(256) pass_b_kernel(
    const float* __restrict__ embed,
    const int* __restrict__ sid)
{
    const int b    = blockIdx.y;
    const int tid  = threadIdx.x;
    const int lane = tid & 31;
    const int wrp  = tid >> 5;          // 0..7
    const int g    = lane >> 2;         // 0..7 row-group within warp
    const int q    = lane & 3;          // float4 slot within row

    __shared__ float4             sA[KK][4];      // 16 KB
    __shared__ int                ssid[2048];     // 8 KB
    __shared__ unsigned long long spack[KK];      // 2 KB
    __shared__ unsigned char      shc[KK];

    #pragma unroll
    for (int i = tid; i < KK * 4; i += 256)
        sA[i >> 2][i & 3] = g_anchor[b][i >> 2][i & 3];
    if (tid < KK) {
        spack[tid] = 0ull;
        shc[tid] = (g_cnt_cp[b][tid] > 0) ? 1 : 0;
    }

    const size_t ev_base = (size_t)b * NN;
    const int blk_base = blockIdx.x * 2048;
    // stage sid tile (coalesced int4; sid is L2-resident after pass_a)
    #pragma unroll
    for (int i = 0; i < 2; i++)
        reinterpret_cast<int4*>(ssid)[tid + i * 256] =
            reinterpret_cast<const int4*>(sid + ev_base + blk_base)[tid + i * 256];
    __syncthreads();

    const float4* ebase = reinterpret_cast<const float4*>(embed) + (ev_base + blk_base) * 4;
    const int wbase = wrp * 256;

    for (int it = 0; it < 32; it += 8) {
        int    rl[8]; int ss[8]; float4 ev[8];
        #pragma unroll
        for (int u = 0; u < 8; u++) {
            rl[u] = wbase + (it + u) * 8 + g;
            ss[u] = ssid[rl[u]];
            ev[u] = ebase[rl[u] * 4 + q];           // unconditional, 512B/warp contiguous
        }
        #pragma unroll
        for (int u = 0; u < 8; u++) {
            const int s = ss[u];
            float d2 = 0.f;
            if (s >= 0 && shc[s]) {
                const float4 av = sA[s][q];
                const float dx = ev[u].x - av.x, dy = ev[u].y - av.y;
                const float dz = ev[u].z - av.z, dw = ev[u].w - av.w;
                d2 = dx * dx + dy * dy + dz * dz + dw * dw;
            }
            // all 32 lanes participate (no divergence): reduce within 4-lane group
            d2 += __shfl_xor_sync(0xffffffff, d2, 1);
            d2 += __shfl_xor_sync(0xffffffff, d2, 2);
            if (q == 0 && s >= 0) {
                unsigned long long pack = 1ull << 44;
                if (shc[s]) pack += __float2ull_rn(d2 * 1048576.f);
                atomicAdd(&spack[s], pack);
            }
        }
    }
    __syncthreads();
    if (tid < KK) {
        const unsigned long long v = spack[tid];
        if (v) {
            atomicAdd(&g_inst[b][tid], (int)(v >> 44));
            const float ds = (float)(v & ((1ull << 44) - 1ull)) * (1.f / 1048576.f);
            if (ds != 0.f) atomicAdd(&g_sd2[b][tid], ds);
        }
    }
}

// ---------------- finalize: one warp per event, parallel loads ----------------
__global__ void __launch_bounds__(256) finalize_kernel(float* __restrict__ out) {
    const int tid  = threadIdx.x;
    const int lane = tid & 31;
    const int b    = tid >> 5;

    __shared__ float s_loss[BB];
    __shared__ int   s_ok[BB];

    float w = 0.f, wf = 0.f, at = 0.f;
    #pragma unroll
    for (int k = lane; k < KK; k += 32) {
        const int c    = g_cnt_cp[b][k];
        const int inst = g_inst[b][k];
        if (c > 0) {
            const float fw = (float)inst;
            w  += fw;
            wf += fw * g_sum_f[b][k] / fmaxf((float)c, 1.f);
            at += g_sd2[b][k] / fmaxf((float)inst, 1.f);
        }
    }
    #pragma unroll
    for (int off = 16; off; off >>= 1) {
        w  += __shfl_down_sync(0xffffffff, w,  off);
        wf += __shfl_down_sync(0xffffffff, wf, off);
        at += __shfl_down_sync(0xffffffff, at, off);
    }

    if (lane == 0) {
        const float pos_bce = wf / fmaxf(w, 1.f);

        const float n_cp  = (float)g_scal_i[b][0];
        const float n_bg  = (float)g_scal_i[b][1];
        const float n_ncp = (float)NN - n_cp;
        const float n_val = (float)NN - n_bg;

        const float neg_bce    = (n_ncp > 0.f) ? g_scal_f[b][0] / fmaxf(n_ncp, 1.f) : 0.f;
        const float bg_bce     = (n_bg  > 0.f) ? g_scal_f[b][1] / fmaxf(n_bg,  1.f) : 0.f;
        const float pos_margin = g_scal_f[b][2] / fmaxf(n_cp, 1.f);
        const float neg_margin = (n_ncp > 0.f) ? g_scal_f[b][3] / fmaxf(n_ncp, 1.f) : 0.f;

        const float beta_loss = 10.f * pos_bce + 3.f * neg_bce + 6.f * bg_bce
                              + 10.f * (pos_margin + neg_margin);

        const int   Mv = g_Mv[b];
        const float fM = (float)Mv;
        const float rep_term = (Mv > 1) ? g_rep[b] / fmaxf(fM * fM, 1.f) : 0.f;

        s_loss[b] = beta_loss + at + rep_term;
        s_ok[b]   = (n_val > 0.f) && (Mv > 0);
    }
    __syncthreads();

    if (tid == 0) {
        float total = 0.f, cnt = 0.f;
        #pragma unroll
        for (int e = 0; e < BB; e++)
            if (s_ok[e]) { total += s_loss[e]; cnt += 1.f; }
        out[0] = (cnt > 0.f) ? total / fmaxf(cnt, 1.f) : 0.f;
    }

    // reset all scratch so the graph replays deterministically
    __syncthreads();
    #pragma unroll
    for (int e = 0; e < BB; e++) {
        g_sum_f[e][tid]  = 0.f;
        g_cnt_cp[e][tid] = 0;
        g_inst[e][tid]   = 0;
        g_first[e][tid]  = 0;
        g_sd2[e][tid]    = 0.f;
    }
    if (tid < BB) {
        g_Mv[tid]  = 0;
        g_rep[tid] = 0.f;
        #pragma unroll
        for (int j = 0; j < 4; j++) g_scal_f[tid][j] = 0.f;
        g_scal_i[tid][0] = 0; g_scal_i[tid][1] = 0;
    }
}

// ---------------- launch (pass_b is 4th -> gets profiled) ----------------
extern "C" void kernel_launch(void* const* d_in, const int* in_sizes, int n_in,
                              void* d_out, int out_size)
{
    (void)in_sizes; (void)n_in; (void)out_size;
    const float* beta  = (const float*)d_in[0];
    const float* embed = (const float*)d_in[1];
    const int*   sid   = (const int*)d_in[2];
    const int*   cp    = (const int*)d_in[3];

    pass_a_kernel<<<dim3(64, BB), 256>>>(beta, sid, cp);
    rep_prep_kernel<<<BB, 1024>>>(embed);
    rep_compute_kernel<<<dim3(REP_BLOCKS, BB), 256>>>();
    pass_b_kernel<<<dim3(128, BB), 256>>>(embed, sid);
    finalize_kernel<<<1, 256>>>((float*)d_out);
}

// round 11
// speedup vs baseline: 1.1227x; 1.1227x over previous
#include <cuda_runtime.h>
#include <cstdint>

#define BB 8
#define NN 262144
#define KK 256
#define DD 16
#define CAP 2048
#define MMAX 1024
#define REP_BLOCKS 64          // rep j-chunk blocks per event
#define RCH 16                 // rep j-chunk size

// ---------------- scratch (device globals; zero == reset state) ----------------
__device__ float  g_sum_f [BB][KK];
__device__ int    g_cnt_cp[BB][KK];
__device__ int    g_inst  [BB][KK];
__device__ int    g_first [BB][KK];   // stores max(NN - li); 0 == no CP
__device__ float  g_sd2   [BB][KK];
__device__ int    g_Mv    [BB];
__device__ int    g_cplist[BB][CAP];
__device__ float  g_scal_f[BB][4];    // 0: sum ce0*~cp, 1: sum ce0*bg, 2: pos_margin, 3: neg_margin
__device__ int    g_scal_i[BB][2];    // 0: n_cp(all), 1: n_bg
__device__ float  g_rep   [BB];

// fast sigmoid + softplus: 2 MUFU + FMA-pipe Newton rcp (seed valid on u in (1,2])
__device__ __forceinline__ void fast_sig_sp(float x, float& p, float& ce0) {
    const float t = __expf(-fabsf(x));
    const float u = 1.f + t;
    float y = __fmaf_rn(u, -0.47058824f, 1.4117647f);
    y = y * __fmaf_rn(-u, y, 2.f);
    y = y * __fmaf_rn(-u, y, 2.f);
    ce0 = fmaxf(x, 0.f) + __logf(u);
    p   = (x >= 0.f) ? y : t * y;
}

// ---------------- pass A: full prefetch (12 LDG.128 in flight), grid 64x8 ----------
__global__ void __launch_bounds__(256) pass_a_kernel(
    const float* __restrict__ beta,
    const int* __restrict__ sid,
    const int* __restrict__ cp)
{
    const int b   = blockIdx.y;
    const int tid = threadIdx.x;

    __shared__ float s_f[KK];
    __shared__ int   s_cnt[KK];
    __shared__ int   s_first[KK];
    __shared__ float s_sc[4];
    __shared__ int   s_si[2];

    s_f[tid] = 0.f; s_cnt[tid] = 0; s_first[tid] = 0;
    if (tid < 4) s_sc[tid] = 0.f;
    if (tid < 2) s_si[tid] = 0;
    __syncthreads();

    float ce0n = 0.f, bg = 0.f, pm = 0.f, nm = 0.f;
    int ncp = 0, nbg = 0;

    const size_t ev_base = (size_t)b * NN;
    const int blk_base = blockIdx.x * 4096;

    int4 s4[4], c4[4];
    float4 x4[4];
    #pragma unroll
    for (int it = 0; it < 4; it++) {
        const int li0 = blk_base + it * 1024 + tid * 4;
        s4[it] = *reinterpret_cast<const int4*>(sid + ev_base + li0);
        c4[it] = *reinterpret_cast<const int4*>(cp  + ev_base + li0);
        x4[it] = *reinterpret_cast<const float4*>(beta + ev_base + li0);
    }

    #pragma unroll
    for (int it = 0; it < 4; it++) {
        const int li0 = blk_base + it * 1024 + tid * 4;
        const int   sv[4] = {s4[it].x, s4[it].y, s4[it].z, s4[it].w};
        const int   cv[4] = {c4[it].x, c4[it].y, c4[it].z, c4[it].w};
        const float xv[4] = {x4[it].x, x4[it].y, x4[it].z, x4[it].w};

        #pragma unroll
        for (int j = 0; j < 4; j++) {
            const int   s = sv[j];
            const float x = xv[j];
            float p, ce0;
            fast_sig_sp(x, p, ce0);

            if (cv[j]) {
                ncp++;
                pm += fmaxf(0.8f - p, 0.f);
                if (s >= 0) {
                    const float om = 1.f - p;
                    atomicAdd(&s_f[s], 0.75f * om * om * (ce0 - x));
                    atomicAdd(&s_cnt[s], 1);
                    atomicMax(&s_first[s], NN - (li0 + j));
                    int pos = atomicAdd(&g_Mv[b], 1);
                    if (pos < CAP) g_cplist[b][pos] = li0 + j;
                }
            } else {
                ce0n += ce0;
                nm += fmaxf(p - 0.2f, 0.f);
            }
            if (s == -1) { nbg++; bg += ce0; }
        }
    }

    atomicAdd(&s_sc[0], ce0n);
    atomicAdd(&s_sc[1], bg);
    atomicAdd(&s_sc[2], pm);
    atomicAdd(&s_sc[3], nm);
    atomicAdd(&s_si[0], ncp);
    atomicAdd(&s_si[1], nbg);
    __syncthreads();

    if (s_f[tid] != 0.f) atomicAdd(&g_sum_f[b][tid], s_f[tid]);
    if (s_cnt[tid])      atomicAdd(&g_cnt_cp[b][tid], s_cnt[tid]);
    if (s_first[tid])    atomicMax(&g_first[b][tid], s_first[tid]);
    if (tid < 4) atomicAdd(&g_scal_f[b][tid], s_sc[tid]);
    if (tid < 2) atomicAdd(&g_scal_i[b][tid], s_si[tid]);
}

// ---------------- pass B: thread-per-row conditional (R2 shape), self-gathered anchors
// 256 thr, grid (128, BB); thread handles 8 rows at stride 256.
__global__ void __launch_bounds__(256) pass_b_kernel(
    const float* __restrict__ embed,
    const int* __restrict__ sid)
{
    const int b   = blockIdx.y;
    const int tid = threadIdx.x;

    __shared__ float4             sA[KK][4];      // 16 KB
    __shared__ int                ssid[2048];     // 8 KB
    __shared__ unsigned long long spack[KK];      // 2 KB
    __shared__ unsigned char      shc[KK];

    const size_t ev_base = (size_t)b * NN;

    if (tid < KK) {
        spack[tid] = 0ull;
        shc[tid] = (g_cnt_cp[b][tid] > 0) ? 1 : 0;
    }
    // self-gather anchors from embed via g_first (L2-hot: ~164 distinct rows/event)
    #pragma unroll
    for (int i = tid; i < KK * 4; i += 256) {
        const int k = i >> 2, q = i & 3;
        const int val = g_first[b][k];
        float4 v = make_float4(0.f, 0.f, 0.f, 0.f);
        if (val > 0)
            v = reinterpret_cast<const float4*>(embed + (ev_base + (NN - val)) * DD)[q];
        sA[k][q] = v;
    }
    const int blk_base = blockIdx.x * 2048;
    #pragma unroll
    for (int i = 0; i < 2; i++)
        reinterpret_cast<int4*>(ssid)[tid + i * 256] =
            reinterpret_cast<const int4*>(sid + ev_base + blk_base)[tid + i * 256];
    __syncthreads();

    int sv[8];
    #pragma unroll
    for (int r = 0; r < 8; r++) sv[r] = ssid[tid + r * 256];

    #pragma unroll 2
    for (int r = 0; r < 8; r++) {
        const int s = sv[r];
        if (s >= 0) {
            unsigned long long pack = 1ull << 44;
            if (shc[s]) {
                const float4* e = reinterpret_cast<const float4*>(
                    embed + (ev_base + blk_base + tid + r * 256) * DD);
                const float4 e0 = e[0], e1 = e[1], e2 = e[2], e3 = e[3];
                const float4 a0 = sA[s][0], a1 = sA[s][1], a2 = sA[s][2], a3 = sA[s][3];
                float d2 = 0.f;
                d2 = __fmaf_rn(e0.x - a0.x, e0.x - a0.x, d2);
                d2 = __fmaf_rn(e0.y - a0.y, e0.y - a0.y, d2);
                d2 = __fmaf_rn(e0.z - a0.z, e0.z - a0.z, d2);
                d2 = __fmaf_rn(e0.w - a0.w, e0.w - a0.w, d2);
                d2 = __fmaf_rn(e1.x - a1.x, e1.x - a1.x, d2);
                d2 = __fmaf_rn(e1.y - a1.y, e1.y - a1.y, d2);
                d2 = __fmaf_rn(e1.z - a1.z, e1.z - a1.z, d2);
                d2 = __fmaf_rn(e1.w - a1.w, e1.w - a1.w, d2);
                d2 = __fmaf_rn(e2.x - a2.x, e2.x - a2.x, d2);
                d2 = __fmaf_rn(e2.y - a2.y, e2.y - a2.y, d2);
                d2 = __fmaf_rn(e2.z - a2.z, e2.z - a2.z, d2);
                d2 = __fmaf_rn(e2.w - a2.w, e2.w - a2.w, d2);
                d2 = __fmaf_rn(e3.x - a3.x, e3.x - a3.x, d2);
                d2 = __fmaf_rn(e3.y - a3.y, e3.y - a3.y, d2);
                d2 = __fmaf_rn(e3.z - a3.z, e3.z - a3.z, d2);
                d2 = __fmaf_rn(e3.w - a3.w, e3.w - a3.w, d2);
                pack += __float2ull_rn(d2 * 1048576.f);
            }
            atomicAdd(&spack[s], pack);
        }
    }
    __syncthreads();
    if (tid < KK) {
        const unsigned long long v = spack[tid];
        if (v) {
            atomicAdd(&g_inst[b][tid], (int)(v >> 44));
            const float ds = (float)(v & ((1ull << 44) - 1ull)) * (1.f / 1048576.f);
            if (ds != 0.f) atomicAdd(&g_sd2[b][tid], ds);
        }
    }
}

// ---------------- repulsion: self-contained (reads g_cplist + embed directly) --------
__global__ void __launch_bounds__(256) rep_compute_kernel(const float* __restrict__ embed) {
    const int b   = blockIdx.y;
    const int tid = threadIdx.x;
    const int j0  = blockIdx.x * RCH;

    const int Mv   = g_Mv[b];
    const int msel = min(Mv, MMAX);
    if (j0 >= msel) return;                        // block-uniform
    const int cnt = min(RCH, msel - j0);

    __shared__ int   sidx[CAP];                    // 8 KB
    __shared__ float sj[RCH * DD];                 // 1 KB
    __shared__ float red[8];

    const int mcol = min(Mv, CAP);
    for (int i = tid; i < CAP; i += 256)
        sidx[i] = (i < mcol) ? g_cplist[b][i] : 0x7fffffff;
    __syncthreads();

    if (Mv > MMAX) {   // statistically never; correctness fallback (select MMAX lowest)
        for (int ksz = 2; ksz <= CAP; ksz <<= 1) {
            for (int j = ksz >> 1; j > 0; j >>= 1) {
                for (int i = tid; i < CAP; i += 256) {
                    int ixj = i ^ j;
                    if (ixj > i) {
                        bool up = ((i & ksz) == 0);
                        int a = sidx[i], c = sidx[ixj];
                        if ((a > c) == up) { sidx[i] = c; sidx[ixj] = a; }
                    }
                }
                __syncthreads();
            }
        }
    }

    const size_t ev_base = (size_t)b * NN;
    for (int t = tid; t < cnt * 4; t += 256) {
        const int j = t >> 2, qq = t & 3;
        reinterpret_cast<float4*>(sj)[t] =
            reinterpret_cast<const float4*>(embed + (ev_base + sidx[j0 + j]) * DD)[qq];
    }
    __syncthreads();

    float acc = 0.f;
    for (int i = tid; i < msel; i += 256) {
        float myE[DD];
        const float4* er = reinterpret_cast<const float4*>(embed + (ev_base + sidx[i]) * DD);
        #pragma unroll
        for (int qq = 0; qq < 4; qq++) {
            const float4 v = er[qq];
            myE[qq * 4 + 0] = v.x; myE[qq * 4 + 1] = v.y;
            myE[qq * 4 + 2] = v.z; myE[qq * 4 + 3] = v.w;
        }
        #pragma unroll
        for (int j = 0; j < RCH; j++) {
            if (j < cnt) {
                float d2 = 0.f;
                #pragma unroll
                for (int d = 0; d < DD; d++) {
                    const float df = myE[d] - sj[j * DD + d];
                    d2 = __fmaf_rn(df, df, d2);
                }
                acc += __expf(-d2);
            }
        }
    }

    #pragma unroll
    for (int off = 16; off; off >>= 1) acc += __shfl_down_sync(0xffffffff, acc, off);
    if ((tid & 31) == 0) red[tid >> 5] = acc;
    __syncthreads();
    if (tid == 0) {
        float tot = 0.f;
        #pragma unroll
        for (int w = 0; w < 8; w++) tot += red[w];
        atomicAdd(&g_rep[b], tot);
    }
}

// ---------------- finalize: warp per event, FULL prefetch (MLP 32) ----------------
__global__ void __launch_bounds__(256) finalize_kernel(float* __restrict__ out) {
    const int tid  = threadIdx.x;
    const int lane = tid & 31;
    const int b    = tid >> 5;

    __shared__ float s_loss[BB];
    __shared__ int   s_ok[BB];

    // prefetch all 8 k-slots x 4 arrays before reducing (32 independent loads)
    int   c[8], inst[8];
    float sf[8], sd[8];
    #pragma unroll
    for (int i = 0; i < 8; i++) {
        const int k = lane + i * 32;
        c[i]    = g_cnt_cp[b][k];
        inst[i] = g_inst[b][k];
        sf[i]   = g_sum_f[b][k];
        sd[i]   = g_sd2[b][k];
    }

    float w = 0.f, wf = 0.f, at = 0.f;
    #pragma unroll
    for (int i = 0; i < 8; i++) {
        if (c[i] > 0) {
            const float fw = (float)inst[i];
            w  += fw;
            wf += fw * sf[i] / fmaxf((float)c[i], 1.f);
            at += sd[i] / fmaxf((float)inst[i], 1.f);
        }
    }
    #pragma unroll
    for (int off = 16; off; off >>= 1) {
        w  += __shfl_down_sync(0xffffffff, w,  off);
        wf += __shfl_down_sync(0xffffffff, wf, off);
        at += __shfl_down_sync(0xffffffff, at, off);
    }

    if (lane == 0) {
        const float pos_bce = wf / fmaxf(w, 1.f);

        const float n_cp  = (float)g_scal_i[b][0];
        const float n_bg  = (float)g_scal_i[b][1];
        const float n_ncp = (float)NN - n_cp;
        const float n_val = (float)NN - n_bg;

        const float neg_bce    = (n_ncp > 0.f) ? g_scal_f[b][0] / fmaxf(n_ncp, 1.f) : 0.f;
        const float bg_bce     = (n_bg  > 0.f) ? g_scal_f[b][1] / fmaxf(n_bg,  1.f) : 0.f;
        const float pos_margin = g_scal_f[b][2] / fmaxf(n_cp, 1.f);
        const float neg_margin = (n_ncp > 0.f) ? g_scal_f[b][3] / fmaxf(n_ncp, 1.f) : 0.f;

        const float beta_loss = 10.f * pos_bce + 3.f * neg_bce + 6.f * bg_bce
                              + 10.f * (pos_margin + neg_margin);

        const int   Mv = g_Mv[b];
        const float fM = (float)Mv;
        const float rep_term = (Mv > 1) ? g_rep[b] / fmaxf(fM * fM, 1.f) : 0.f;

        s_loss[b] = beta_loss + at + rep_term;
        s_ok[b]   = (n_val > 0.f) && (Mv > 0);
    }
    __syncthreads();

    if (tid == 0) {
        float total = 0.f, cnt = 0.f;
        #pragma unroll
        for (int e = 0; e < BB; e++)
            if (s_ok[e]) { total += s_loss[e]; cnt += 1.f; }
        out[0] = (cnt > 0.f) ? total / fmaxf(cnt, 1.f) : 0.f;
    }

    // reset all scratch so the graph replays deterministically (independent stores)
    #pragma unroll
    for (int e = 0; e < BB; e++) {
        g_sum_f[e][tid]  = 0.f;
        g_cnt_cp[e][tid] = 0;
        g_inst[e][tid]   = 0;
        g_first[e][tid]  = 0;
        g_sd2[e][tid]    = 0.f;
    }
    if (tid < BB) {
        g_Mv[tid]  = 0;
        g_rep[tid] = 0.f;
        #pragma unroll
        for (int j = 0; j < 4; j++) g_scal_f[tid][j] = 0.f;
        g_scal_i[tid][0] = 0; g_scal_i[tid][1] = 0;
    }
}

// ---------------- launch: 4 kernels (pass_b at stream idx 1 -> profiled by -s 5) ----
extern "C" void kernel_launch(void* const* d_in, const int* in_sizes, int n_in,
                              void* d_out, int out_size)
{
    (void)in_sizes; (void)n_in; (void)out_size;
    const float* beta  = (const float*)d_in[0];
    const float* embed = (const float*)d_in[1];
    const int*   sid   = (const int*)d_in[2];
    const int*   cp    = (const int*)d_in[3];

    pass_a_kernel<<<dim3(64, BB), 256>>>(beta, sid, cp);
    pass_b_kernel<<<dim3(128, BB), 256>>>(embed, sid);
    rep_compute_kernel<<<dim3(REP_BLOCKS, BB), 256>>>(embed);
    finalize_kernel<<<1, 256>>>((float*)d_out);
}

// round 12
// speedup vs baseline: 1.1466x; 1.0212x over previous
#include <cuda_runtime.h>
#include <cstdint>

#define BB 8
#define NN 262144
#define KK 256
#define DD 16
#define CAP 2048
#define MMAX 1024
#define REP_BLOCKS 64          // rep j-chunk blocks per event
#define RCH 16                 // rep j-chunk size

// ---------------- scratch (device globals; zero == reset state) ----------------
__device__ float  g_sum_f [BB][KK];
__device__ int    g_cnt_cp[BB][KK];
__device__ int    g_inst  [BB][KK];
__device__ int    g_first [BB][KK];   // stores max(NN - li); 0 == no CP
__device__ float  g_sd2   [BB][KK];
__device__ int    g_Mv    [BB];
__device__ int    g_cplist[BB][CAP];
__device__ float  g_scal_f[BB][4];    // 0: sum ce0*~cp, 1: sum ce0*bg, 2: pos_margin, 3: neg_margin
__device__ int    g_scal_i[BB][2];    // 0: n_cp(all), 1: n_bg
__device__ float  g_rep   [BB];

// fast sigmoid + softplus: 2 MUFU + FMA-pipe Newton rcp (seed valid on u in (1,2])
__device__ __forceinline__ void fast_sig_sp(float x, float& p, float& ce0) {
    const float t = __expf(-fabsf(x));
    const float u = 1.f + t;
    float y = __fmaf_rn(u, -0.47058824f, 1.4117647f);
    y = y * __fmaf_rn(-u, y, 2.f);
    y = y * __fmaf_rn(-u, y, 2.f);
    ce0 = fmaxf(x, 0.f) + __logf(u);
    p   = (x >= 0.f) ? y : t * y;
}

// ---------------- pass A: full prefetch (12 LDG.128 in flight), grid 64x8 ----------
__global__ void __launch_bounds__(256) pass_a_kernel(
    const float* __restrict__ beta,
    const int* __restrict__ sid,
    const int* __restrict__ cp)
{
    const int b   = blockIdx.y;
    const int tid = threadIdx.x;

    __shared__ float s_f[KK];
    __shared__ int   s_cnt[KK];
    __shared__ int   s_first[KK];
    __shared__ float s_sc[4];
    __shared__ int   s_si[2];

    s_f[tid] = 0.f; s_cnt[tid] = 0; s_first[tid] = 0;
    if (tid < 4) s_sc[tid] = 0.f;
    if (tid < 2) s_si[tid] = 0;
    __syncthreads();

    float ce0n = 0.f, bg = 0.f, pm = 0.f, nm = 0.f;
    int ncp = 0, nbg = 0;

    const size_t ev_base = (size_t)b * NN;
    const int blk_base = blockIdx.x * 4096;

    int4 s4[4], c4[4];
    float4 x4[4];
    #pragma unroll
    for (int it = 0; it < 4; it++) {
        const int li0 = blk_base + it * 1024 + tid * 4;
        s4[it] = *reinterpret_cast<const int4*>(sid + ev_base + li0);
        c4[it] = *reinterpret_cast<const int4*>(cp  + ev_base + li0);
        x4[it] = *reinterpret_cast<const float4*>(beta + ev_base + li0);
    }

    #pragma unroll
    for (int it = 0; it < 4; it++) {
        const int li0 = blk_base + it * 1024 + tid * 4;
        const int   sv[4] = {s4[it].x, s4[it].y, s4[it].z, s4[it].w};
        const int   cv[4] = {c4[it].x, c4[it].y, c4[it].z, c4[it].w};
        const float xv[4] = {x4[it].x, x4[it].y, x4[it].z, x4[it].w};

        #pragma unroll
        for (int j = 0; j < 4; j++) {
            const int   s = sv[j];
            const float x = xv[j];
            float p, ce0;
            fast_sig_sp(x, p, ce0);

            if (cv[j]) {
                ncp++;
                pm += fmaxf(0.8f - p, 0.f);
                if (s >= 0) {
                    const float om = 1.f - p;
                    atomicAdd(&s_f[s], 0.75f * om * om * (ce0 - x));
                    atomicAdd(&s_cnt[s], 1);
                    atomicMax(&s_first[s], NN - (li0 + j));
                    int pos = atomicAdd(&g_Mv[b], 1);
                    if (pos < CAP) g_cplist[b][pos] = li0 + j;
                }
            } else {
                ce0n += ce0;
                nm += fmaxf(p - 0.2f, 0.f);
            }
            if (s == -1) { nbg++; bg += ce0; }
        }
    }

    atomicAdd(&s_sc[0], ce0n);
    atomicAdd(&s_sc[1], bg);
    atomicAdd(&s_sc[2], pm);
    atomicAdd(&s_sc[3], nm);
    atomicAdd(&s_si[0], ncp);
    atomicAdd(&s_si[1], nbg);
    __syncthreads();

    if (s_f[tid] != 0.f) atomicAdd(&g_sum_f[b][tid], s_f[tid]);
    if (s_cnt[tid])      atomicAdd(&g_cnt_cp[b][tid], s_cnt[tid]);
    if (s_first[tid])    atomicMax(&g_first[b][tid], s_first[tid]);
    if (tid < 4) atomicAdd(&g_scal_f[b][tid], s_sc[tid]);
    if (tid < 2) atomicAdd(&g_scal_i[b][tid], s_si[tid]);
}

// ---------------- pass B: R2 loop shape (measured best), gated packed atomic --------
// 256 thr, grid (64, BB): 4096 rows/block, 16 rows/thread at stride 256.
__global__ void __launch_bounds__(256) pass_b_kernel(
    const float* __restrict__ embed,
    const int* __restrict__ sid)
{
    const int b   = blockIdx.y;
    const int tid = threadIdx.x;

    __shared__ float4             sA[KK][4];      // 16 KB
    __shared__ unsigned long long spack[KK];      // 2 KB
    __shared__ unsigned char      shc[KK];

    const size_t ev_base = (size_t)b * NN;

    if (tid < KK) {
        spack[tid] = 0ull;
        shc[tid] = (g_cnt_cp[b][tid] > 0) ? 1 : 0;
    }
    // self-gather anchors from embed via g_first (L2-hot: ~164 distinct rows/event)
    #pragma unroll
    for (int i = tid; i < KK * 4; i += 256) {
        const int k = i >> 2, q = i & 3;
        const int val = g_first[b][k];
        float4 v = make_float4(0.f, 0.f, 0.f, 0.f);
        if (val > 0)
            v = reinterpret_cast<const float4*>(embed + (ev_base + (NN - val)) * DD)[q];
        sA[k][q] = v;
    }
    __syncthreads();

    const int blk_base = blockIdx.x * 4096;

    for (int it = 0; it < 16; it++) {
        const int row = blk_base + it * 256 + tid;
        const int s = sid[ev_base + row];            // scalar load, sid L2-hot
        if (s >= 0 && shc[s]) {
            const float4* e = reinterpret_cast<const float4*>(embed + (ev_base + row) * DD);
            const float4 e0 = e[0], e1 = e[1], e2 = e[2], e3 = e[3];
            const float4 a0 = sA[s][0], a1 = sA[s][1], a2 = sA[s][2], a3 = sA[s][3];
            float d2 = 0.f;
            d2 = __fmaf_rn(e0.x - a0.x, e0.x - a0.x, d2);
            d2 = __fmaf_rn(e0.y - a0.y, e0.y - a0.y, d2);
            d2 = __fmaf_rn(e0.z - a0.z, e0.z - a0.z, d2);
            d2 = __fmaf_rn(e0.w - a0.w, e0.w - a0.w, d2);
            d2 = __fmaf_rn(e1.x - a1.x, e1.x - a1.x, d2);
            d2 = __fmaf_rn(e1.y - a1.y, e1.y - a1.y, d2);
            d2 = __fmaf_rn(e1.z - a1.z, e1.z - a1.z, d2);
            d2 = __fmaf_rn(e1.w - a1.w, e1.w - a1.w, d2);
            d2 = __fmaf_rn(e2.x - a2.x, e2.x - a2.x, d2);
            d2 = __fmaf_rn(e2.y - a2.y, e2.y - a2.y, d2);
            d2 = __fmaf_rn(e2.z - a2.z, e2.z - a2.z, d2);
            d2 = __fmaf_rn(e2.w - a2.w, e2.w - a2.w, d2);
            d2 = __fmaf_rn(e3.x - a3.x, e3.x - a3.x, d2);
            d2 = __fmaf_rn(e3.y - a3.y, e3.y - a3.y, d2);
            d2 = __fmaf_rn(e3.z - a3.z, e3.z - a3.z, d2);
            d2 = __fmaf_rn(e3.w - a3.w, e3.w - a3.w, d2);
            atomicAdd(&spack[s], (1ull << 44) + __float2ull_rn(d2 * 1048576.f));
        }
    }
    __syncthreads();
    if (tid < KK) {
        const unsigned long long v = spack[tid];
        if (v) {
            atomicAdd(&g_inst[b][tid], (int)(v >> 44));
            const float ds = (float)(v & ((1ull << 44) - 1ull)) * (1.f / 1048576.f);
            if (ds != 0.f) atomicAdd(&g_sd2[b][tid], ds);
        }
    }
}

// ---------------- repulsion: self-contained (reads g_cplist + embed directly) --------
__global__ void __launch_bounds__(256) rep_compute_kernel(const float* __restrict__ embed) {
    const int b   = blockIdx.y;
    const int tid = threadIdx.x;
    const int j0  = blockIdx.x * RCH;

    const int Mv   = g_Mv[b];
    const int msel = min(Mv, MMAX);
    if (j0 >= msel) return;                        // block-uniform
    const int cnt = min(RCH, msel - j0);

    __shared__ int   sidx[CAP];                    // 8 KB
    __shared__ float sj[RCH * DD];                 // 1 KB
    __shared__ float red[8];

    const int mcol = min(Mv, CAP);
    for (int i = tid; i < CAP; i += 256)
        sidx[i] = (i < mcol) ? g_cplist[b][i] : 0x7fffffff;
    __syncthreads();

    if (Mv > MMAX) {   // statistically never; correctness fallback (select MMAX lowest)
        for (int ksz = 2; ksz <= CAP; ksz <<= 1) {
            for (int j = ksz >> 1; j > 0; j >>= 1) {
                for (int i = tid; i < CAP; i += 256) {
                    int ixj = i ^ j;
                    if (ixj > i) {
                        bool up = ((i & ksz) == 0);
                        int a = sidx[i], c = sidx[ixj];
                        if ((a > c) == up) { sidx[i] = c; sidx[ixj] = a; }
                    }
                }
                __syncthreads();
            }
        }
    }

    const size_t ev_base = (size_t)b * NN;
    for (int t = tid; t < cnt * 4; t += 256) {
        const int j = t >> 2, qq = t & 3;
        reinterpret_cast<float4*>(sj)[t] =
            reinterpret_cast<const float4*>(embed + (ev_base + sidx[j0 + j]) * DD)[qq];
    }
    __syncthreads();

    float acc = 0.f;
    for (int i = tid; i < msel; i += 256) {
        float myE[DD];
        const float4* er = reinterpret_cast<const float4*>(embed + (ev_base + sidx[i]) * DD);
        #pragma unroll
        for (int qq = 0; qq < 4; qq++) {
            const float4 v = er[qq];
            myE[qq * 4 + 0] = v.x; myE[qq * 4 + 1] = v.y;
            myE[qq * 4 + 2] = v.z; myE[qq * 4 + 3] = v.w;
        }
        #pragma unroll
        for (int j = 0; j < RCH; j++) {
            if (j < cnt) {
                float d2 = 0.f;
                #pragma unroll
                for (int d = 0; d < DD; d++) {
                    const float df = myE[d] - sj[j * DD + d];
                    d2 = __fmaf_rn(df, df, d2);
                }
                acc += __expf(-d2);
            }
        }
    }

    #pragma unroll
    for (int off = 16; off; off >>= 1) acc += __shfl_down_sync(0xffffffff, acc, off);
    if ((tid & 31) == 0) red[tid >> 5] = acc;
    __syncthreads();
    if (tid == 0) {
        float tot = 0.f;
        #pragma unroll
        for (int w = 0; w < 8; w++) tot += red[w];
        atomicAdd(&g_rep[b], tot);
    }
}

// ---------------- finalize: 1024 thr; warp b (of first 8) per event; wide reset -----
__global__ void __launch_bounds__(1024) finalize_kernel(float* __restrict__ out) {
    const int tid  = threadIdx.x;
    const int lane = tid & 31;
    const int wid  = tid >> 5;

    __shared__ float s_loss[BB];
    __shared__ int   s_ok[BB];

    if (wid < BB) {
        const int b = wid;
        int   c[8], inst[8];
        float sf[8], sd[8];
        #pragma unroll
        for (int i = 0; i < 8; i++) {
            const int k = lane + i * 32;
            c[i]    = g_cnt_cp[b][k];
            inst[i] = g_inst[b][k];
            sf[i]   = g_sum_f[b][k];
            sd[i]   = g_sd2[b][k];
        }

        float w = 0.f, wf = 0.f, at = 0.f;
        #pragma unroll
        for (int i = 0; i < 8; i++) {
            if (c[i] > 0) {
                const float fw = (float)inst[i];
                w  += fw;
                wf += fw * sf[i] / fmaxf((float)c[i], 1.f);
                at += sd[i] / fmaxf((float)inst[i], 1.f);
            }
        }
        #pragma unroll
        for (int off = 16; off; off >>= 1) {
            w  += __shfl_down_sync(0xffffffff, w,  off);
            wf += __shfl_down_sync(0xffffffff, wf, off);
            at += __shfl_down_sync(0xffffffff, at, off);
        }

        if (lane == 0) {
            const float pos_bce = wf / fmaxf(w, 1.f);

            const float n_cp  = (float)g_scal_i[b][0];
            const float n_bg  = (float)g_scal_i[b][1];
            const float n_ncp = (float)NN - n_cp;
            const float n_val = (float)NN - n_bg;

            const float neg_bce    = (n_ncp > 0.f) ? g_scal_f[b][0] / fmaxf(n_ncp, 1.f) : 0.f;
            const float bg_bce     = (n_bg  > 0.f) ? g_scal_f[b][1] / fmaxf(n_bg,  1.f) : 0.f;
            const float pos_margin = g_scal_f[b][2] / fmaxf(n_cp, 1.f);
            const float neg_margin = (n_ncp > 0.f) ? g_scal_f[b][3] / fmaxf(n_ncp, 1.f) : 0.f;

            const float beta_loss = 10.f * pos_bce + 3.f * neg_bce + 6.f * bg_bce
                                  + 10.f * (pos_margin + neg_margin);

            const int   Mv = g_Mv[b];
            const float fM = (float)Mv;
            const float rep_term = (Mv > 1) ? g_rep[b] / fmaxf(fM * fM, 1.f) : 0.f;

            s_loss[b] = beta_loss + at + rep_term;
            s_ok[b]   = (n_val > 0.f) && (Mv > 0);
        }
    }
    __syncthreads();

    if (tid == 0) {
        float total = 0.f, cnt = 0.f;
        #pragma unroll
        for (int e = 0; e < BB; e++)
            if (s_ok[e]) { total += s_loss[e]; cnt += 1.f; }
        out[0] = (cnt > 0.f) ? total / fmaxf(cnt, 1.f) : 0.f;
    }

    // wide reset: 1024 threads cover BB*KK = 2048 slots in 2 strides
    #pragma unroll
    for (int t = tid; t < BB * KK; t += 1024) {
        const int e = t >> 8, k = t & 255;
        g_sum_f[e][k]  = 0.f;
        g_cnt_cp[e][k] = 0;
        g_inst[e][k]   = 0;
        g_first[e][k]  = 0;
        g_sd2[e][k]    = 0.f;
    }
    if (tid < BB) {
        g_Mv[tid]  = 0;
        g_rep[tid] = 0.f;
        #pragma unroll
        for (int j = 0; j < 4; j++) g_scal_f[tid][j] = 0.f;
        g_scal_i[tid][0] = 0; g_scal_i[tid][1] = 0;
    }
}

// ---------------- launch ----------------
extern "C" void kernel_launch(void* const* d_in, const int* in_sizes, int n_in,
                              void* d_out, int out_size)
{
    (void)in_sizes; (void)n_in; (void)out_size;
    const float* beta  = (const float*)d_in[0];
    const float* embed = (const float*)d_in[1];
    const int*   sid   = (const int*)d_in[2];
    const int*   cp    = (const int*)d_in[3];

    pass_a_kernel<<<dim3(64, BB), 256>>>(beta, sid, cp);
    pass_b_kernel<<<dim3(64, BB), 256>>>(embed, sid);
    rep_compute_kernel<<<dim3(REP_BLOCKS, BB), 256>>>(embed);
    finalize_kernel<<<1, 1024>>>((float*)d_out);
}

// round 13
// speedup vs baseline: 1.1751x; 1.0249x over previous
#include <cuda_runtime.h>
#include <cstdint>

#define BB 8
#define NN 262144
#define KK 256
#define DD 16
#define CAP 2048
#define MMAX 1024
#define REP_BLOCKS 64          // rep j-chunk blocks per event
#define RCH 16                 // rep j-chunk size
#define PB_CHUNKS 18           // pass_b chunks per event (18*8 = 144 blocks = one wave)
#define PB_CH 14564            // ceil(NN / PB_CHUNKS)

// ---------------- scratch (device globals; zero == reset state) ----------------
__device__ float  g_sum_f [BB][KK];
__device__ int    g_cnt_cp[BB][KK];
__device__ int    g_inst  [BB][KK];
__device__ int    g_first [BB][KK];   // stores max(NN - li); 0 == no CP
__device__ float  g_sd2   [BB][KK];
__device__ int    g_Mv    [BB];
__device__ int    g_cplist[BB][CAP];
__device__ float  g_scal_f[BB][4];    // 0: sum ce0*~cp, 1: sum ce0*bg, 2: pos_margin, 3: neg_margin
__device__ int    g_scal_i[BB][2];    // 0: n_cp(all), 1: n_bg
__device__ float  g_rep   [BB];

// fast sigmoid + softplus: 2 MUFU + FMA-pipe Newton rcp (seed valid on u in (1,2])
__device__ __forceinline__ void fast_sig_sp(float x, float& p, float& ce0) {
    const float t = __expf(-fabsf(x));
    const float u = 1.f + t;
    float y = __fmaf_rn(u, -0.47058824f, 1.4117647f);
    y = y * __fmaf_rn(-u, y, 2.f);
    y = y * __fmaf_rn(-u, y, 2.f);
    ce0 = fmaxf(x, 0.f) + __logf(u);
    p   = (x >= 0.f) ? y : t * y;
}

// ---------------- pass A: full prefetch (12 LDG.128 in flight), grid 64x8 ----------
__global__ void __launch_bounds__(256) pass_a_kernel(
    const float* __restrict__ beta,
    const int* __restrict__ sid,
    const int* __restrict__ cp)
{
    const int b   = blockIdx.y;
    const int tid = threadIdx.x;

    __shared__ float s_f[KK];
    __shared__ int   s_cnt[KK];
    __shared__ int   s_first[KK];
    __shared__ float s_sc[4];
    __shared__ int   s_si[2];

    s_f[tid] = 0.f; s_cnt[tid] = 0; s_first[tid] = 0;
    if (tid < 4) s_sc[tid] = 0.f;
    if (tid < 2) s_si[tid] = 0;
    __syncthreads();

    float ce0n = 0.f, bg = 0.f, pm = 0.f, nm = 0.f;
    int ncp = 0, nbg = 0;

    const size_t ev_base = (size_t)b * NN;
    const int blk_base = blockIdx.x * 4096;

    int4 s4[4], c4[4];
    float4 x4[4];
    #pragma unroll
    for (int it = 0; it < 4; it++) {
        const int li0 = blk_base + it * 1024 + tid * 4;
        s4[it] = *reinterpret_cast<const int4*>(sid + ev_base + li0);
        c4[it] = *reinterpret_cast<const int4*>(cp  + ev_base + li0);
        x4[it] = *reinterpret_cast<const float4*>(beta + ev_base + li0);
    }

    #pragma unroll
    for (int it = 0; it < 4; it++) {
        const int li0 = blk_base + it * 1024 + tid * 4;
        const int   sv[4] = {s4[it].x, s4[it].y, s4[it].z, s4[it].w};
        const int   cv[4] = {c4[it].x, c4[it].y, c4[it].z, c4[it].w};
        const float xv[4] = {x4[it].x, x4[it].y, x4[it].z, x4[it].w};

        #pragma unroll
        for (int j = 0; j < 4; j++) {
            const int   s = sv[j];
            const float x = xv[j];
            float p, ce0;
            fast_sig_sp(x, p, ce0);

            if (cv[j]) {
                ncp++;
                pm += fmaxf(0.8f - p, 0.f);
                if (s >= 0) {
                    const float om = 1.f - p;
                    atomicAdd(&s_f[s], 0.75f * om * om * (ce0 - x));
                    atomicAdd(&s_cnt[s], 1);
                    atomicMax(&s_first[s], NN - (li0 + j));
                    int pos = atomicAdd(&g_Mv[b], 1);
                    if (pos < CAP) g_cplist[b][pos] = li0 + j;
                }
            } else {
                ce0n += ce0;
                nm += fmaxf(p - 0.2f, 0.f);
            }
            if (s == -1) { nbg++; bg += ce0; }
        }
    }

    atomicAdd(&s_sc[0], ce0n);
    atomicAdd(&s_sc[1], bg);
    atomicAdd(&s_sc[2], pm);
    atomicAdd(&s_sc[3], nm);
    atomicAdd(&s_si[0], ncp);
    atomicAdd(&s_si[1], nbg);
    __syncthreads();

    if (s_f[tid] != 0.f) atomicAdd(&g_sum_f[b][tid], s_f[tid]);
    if (s_cnt[tid])      atomicAdd(&g_cnt_cp[b][tid], s_cnt[tid]);
    if (s_first[tid])    atomicMax(&g_first[b][tid], s_first[tid]);
    if (tid < 4) atomicAdd(&g_scal_f[b][tid], s_sc[tid]);
    if (tid < 2) atomicAdd(&g_scal_i[b][tid], s_si[tid]);
}

// ---------------- pass B: oe=1 (144 blocks = one wave, 1 CTA/SM), 1024 thr ----------
// Each block: event b = blk/18, rows [chunk*PB_CH, min(+PB_CH, NN)), ~14.2 rows/thread.
__global__ void __launch_bounds__(1024) pass_b_kernel(
    const float* __restrict__ embed,
    const int* __restrict__ sid)
{
    const int blk   = blockIdx.x;
    const int b     = blk / PB_CHUNKS;
    const int chunk = blk % PB_CHUNKS;
    const int tid   = threadIdx.x;

    __shared__ float4             sA[KK][4];      // 16 KB
    __shared__ unsigned long long spack[KK];      // 2 KB
    __shared__ unsigned char      shc[KK];

    const size_t ev_base = (size_t)b * NN;

    if (tid < KK) {
        spack[tid] = 0ull;
        shc[tid] = (g_cnt_cp[b][tid] > 0) ? 1 : 0;
    }
    // self-gather anchors (1024 threads cover KK*4 = 1024 exactly)
    {
        const int k = tid >> 2, q = tid & 3;
        const int val = g_first[b][k];
        float4 v = make_float4(0.f, 0.f, 0.f, 0.f);
        if (val > 0)
            v = reinterpret_cast<const float4*>(embed + (ev_base + (NN - val)) * DD)[q];
        sA[k][q] = v;
    }
    __syncthreads();

    const int start = chunk * PB_CH;
    const int end   = min(start + PB_CH, NN);

    #pragma unroll 2
    for (int row = start + tid; row < end; row += 1024) {
        const int s = sid[ev_base + row];
        if (s >= 0 && shc[s]) {
            const float4* e = reinterpret_cast<const float4*>(embed + (ev_base + row) * DD);
            const float4 e0 = e[0], e1 = e[1], e2 = e[2], e3 = e[3];
            const float4 a0 = sA[s][0], a1 = sA[s][1], a2 = sA[s][2], a3 = sA[s][3];
            float d2 = 0.f;
            d2 = __fmaf_rn(e0.x - a0.x, e0.x - a0.x, d2);
            d2 = __fmaf_rn(e0.y - a0.y, e0.y - a0.y, d2);
            d2 = __fmaf_rn(e0.z - a0.z, e0.z - a0.z, d2);
            d2 = __fmaf_rn(e0.w - a0.w, e0.w - a0.w, d2);
            d2 = __fmaf_rn(e1.x - a1.x, e1.x - a1.x, d2);
            d2 = __fmaf_rn(e1.y - a1.y, e1.y - a1.y, d2);
            d2 = __fmaf_rn(e1.z - a1.z, e1.z - a1.z, d2);
            d2 = __fmaf_rn(e1.w - a1.w, e1.w - a1.w, d2);
            d2 = __fmaf_rn(e2.x - a2.x, e2.x - a2.x, d2);
            d2 = __fmaf_rn(e2.y - a2.y, e2.y - a2.y, d2);
            d2 = __fmaf_rn(e2.z - a2.z, e2.z - a2.z, d2);
            d2 = __fmaf_rn(e2.w - a2.w, e2.w - a2.w, d2);
            d2 = __fmaf_rn(e3.x - a3.x, e3.x - a3.x, d2);
            d2 = __fmaf_rn(e3.y - a3.y, e3.y - a3.y, d2);
            d2 = __fmaf_rn(e3.z - a3.z, e3.z - a3.z, d2);
            d2 = __fmaf_rn(e3.w - a3.w, e3.w - a3.w, d2);
            atomicAdd(&spack[s], (1ull << 44) + __float2ull_rn(d2 * 1048576.f));
        }
    }
    __syncthreads();
    if (tid < KK) {
        const unsigned long long v = spack[tid];
        if (v) {
            atomicAdd(&g_inst[b][tid], (int)(v >> 44));
            const float ds = (float)(v & ((1ull << 44) - 1ull)) * (1.f / 1048576.f);
            if (ds != 0.f) atomicAdd(&g_sd2[b][tid], ds);
        }
    }
}

// ---------------- repulsion: self-contained (reads g_cplist + embed directly) --------
__global__ void __launch_bounds__(256) rep_compute_kernel(const float* __restrict__ embed) {
    const int b   = blockIdx.y;
    const int tid = threadIdx.x;
    const int j0  = blockIdx.x * RCH;

    const int Mv   = g_Mv[b];
    const int msel = min(Mv, MMAX);
    if (j0 >= msel) return;                        // block-uniform
    const int cnt = min(RCH, msel - j0);

    __shared__ int   sidx[CAP];                    // 8 KB
    __shared__ float sj[RCH * DD];                 // 1 KB
    __shared__ float red[8];

    const int mcol = min(Mv, CAP);
    for (int i = tid; i < CAP; i += 256)
        sidx[i] = (i < mcol) ? g_cplist[b][i] : 0x7fffffff;
    __syncthreads();

    if (Mv > MMAX) {   // statistically never; correctness fallback (select MMAX lowest)
        for (int ksz = 2; ksz <= CAP; ksz <<= 1) {
            for (int j = ksz >> 1; j > 0; j >>= 1) {
                for (int i = tid; i < CAP; i += 256) {
                    int ixj = i ^ j;
                    if (ixj > i) {
                        bool up = ((i & ksz) == 0);
                        int a = sidx[i], c = sidx[ixj];
                        if ((a > c) == up) { sidx[i] = c; sidx[ixj] = a; }
                    }
                }
                __syncthreads();
            }
        }
    }

    const size_t ev_base = (size_t)b * NN;
    for (int t = tid; t < cnt * 4; t += 256) {
        const int j = t >> 2, qq = t & 3;
        reinterpret_cast<float4*>(sj)[t] =
            reinterpret_cast<const float4*>(embed + (ev_base + sidx[j0 + j]) * DD)[qq];
    }
    __syncthreads();

    float acc = 0.f;
    for (int i = tid; i < msel; i += 256) {
        float myE[DD];
        const float4* er = reinterpret_cast<const float4*>(embed + (ev_base + sidx[i]) * DD);
        #pragma unroll
        for (int qq = 0; qq < 4; qq++) {
            const float4 v = er[qq];
            myE[qq * 4 + 0] = v.x; myE[qq * 4 + 1] = v.y;
            myE[qq * 4 + 2] = v.z; myE[qq * 4 + 3] = v.w;
        }
        #pragma unroll
        for (int j = 0; j < RCH; j++) {
            if (j < cnt) {
                float d2 = 0.f;
                #pragma unroll
                for (int d = 0; d < DD; d++) {
                    const float df = myE[d] - sj[j * DD + d];
                    d2 = __fmaf_rn(df, df, d2);
                }
                acc += __expf(-d2);
            }
        }
    }

    #pragma unroll
    for (int off = 16; off; off >>= 1) acc += __shfl_down_sync(0xffffffff, acc, off);
    if ((tid & 31) == 0) red[tid >> 5] = acc;
    __syncthreads();
    if (tid == 0) {
        float tot = 0.f;
        #pragma unroll
        for (int w = 0; w < 8; w++) tot += red[w];
        atomicAdd(&g_rep[b], tot);
    }
}

// ---------------- finalize: 1024 thr; warp b (of first 8) per event; wide reset -----
__global__ void __launch_bounds__(1024) finalize_kernel(float* __restrict__ out) {
    const int tid  = threadIdx.x;
    const int lane = tid & 31;
    const int wid  = tid >> 5;

    __shared__ float s_loss[BB];
    __shared__ int   s_ok[BB];

    if (wid < BB) {
        const int b = wid;
        int   c[8], inst[8];
        float sf[8], sd[8];
        #pragma unroll
        for (int i = 0; i < 8; i++) {
            const int k = lane + i * 32;
            c[i]    = g_cnt_cp[b][k];
            inst[i] = g_inst[b][k];
            sf[i]   = g_sum_f[b][k];
            sd[i]   = g_sd2[b][k];
        }

        float w = 0.f, wf = 0.f, at = 0.f;
        #pragma unroll
        for (int i = 0; i < 8; i++) {
            if (c[i] > 0) {
                const float fw = (float)inst[i];
                w  += fw;
                wf += fw * sf[i] / fmaxf((float)c[i], 1.f);
                at += sd[i] / fmaxf((float)inst[i], 1.f);
            }
        }
        #pragma unroll
        for (int off = 16; off; off >>= 1) {
            w  += __shfl_down_sync(0xffffffff, w,  off);
            wf += __shfl_down_sync(0xffffffff, wf, off);
            at += __shfl_down_sync(0xffffffff, at, off);
        }

        if (lane == 0) {
            const float pos_bce = wf / fmaxf(w, 1.f);

            const float n_cp  = (float)g_scal_i[b][0];
            const float n_bg  = (float)g_scal_i[b][1];
            const float n_ncp = (float)NN - n_cp;
            const float n_val = (float)NN - n_bg;

            const float neg_bce    = (n_ncp > 0.f) ? g_scal_f[b][0] / fmaxf(n_ncp, 1.f) : 0.f;
            const float bg_bce     = (n_bg  > 0.f) ? g_scal_f[b][1] / fmaxf(n_bg,  1.f) : 0.f;
            const float pos_margin = g_scal_f[b][2] / fmaxf(n_cp, 1.f);
            const float neg_margin = (n_ncp > 0.f) ? g_scal_f[b][3] / fmaxf(n_ncp, 1.f) : 0.f;

            const float beta_loss = 10.f * pos_bce + 3.f * neg_bce + 6.f * bg_bce
                                  + 10.f * (pos_margin + neg_margin);

            const int   Mv = g_Mv[b];
            const float fM = (float)Mv;
            const float rep_term = (Mv > 1) ? g_rep[b] / fmaxf(fM * fM, 1.f) : 0.f;

            s_loss[b] = beta_loss + at + rep_term;
            s_ok[b]   = (n_val > 0.f) && (Mv > 0);
        }
    }
    __syncthreads();

    if (tid == 0) {
        float total = 0.f, cnt = 0.f;
        #pragma unroll
        for (int e = 0; e < BB; e++)
            if (s_ok[e]) { total += s_loss[e]; cnt += 1.f; }
        out[0] = (cnt > 0.f) ? total / fmaxf(cnt, 1.f) : 0.f;
    }

    // wide reset: 1024 threads cover BB*KK = 2048 slots in 2 strides
    #pragma unroll
    for (int t = tid; t < BB * KK; t += 1024) {
        const int e = t >> 8, k = t & 255;
        g_sum_f[e][k]  = 0.f;
        g_cnt_cp[e][k] = 0;
        g_inst[e][k]   = 0;
        g_first[e][k]  = 0;
        g_sd2[e][k]    = 0.f;
    }
    if (tid < BB) {
        g_Mv[tid]  = 0;
        g_rep[tid] = 0.f;
        #pragma unroll
        for (int j = 0; j < 4; j++) g_scal_f[tid][j] = 0.f;
        g_scal_i[tid][0] = 0; g_scal_i[tid][1] = 0;
    }
}

// ---------------- launch ----------------
extern "C" void kernel_launch(void* const* d_in, const int* in_sizes, int n_in,
                              void* d_out, int out_size)
{
    (void)in_sizes; (void)n_in; (void)out_size;
    const float* beta  = (const float*)d_in[0];
    const float* embed = (const float*)d_in[1];
    const int*   sid   = (const int*)d_in[2];
    const int*   cp    = (const int*)d_in[3];

    pass_a_kernel<<<dim3(64, BB), 256>>>(beta, sid, cp);
    pass_b_kernel<<<PB_CHUNKS * BB, 1024>>>(embed, sid);
    rep_compute_kernel<<<dim3(REP_BLOCKS, BB), 256>>>(embed);
    finalize_kernel<<<1, 1024>>>((float*)d_out);
}

// round 14
// speedup vs baseline: 1.1812x; 1.0052x over previous
#include <cuda_runtime.h>
#include <cstdint>

#define BB 8
#define NN 262144
#define KK 256
#define DD 16
#define CAP 2048
#define MMAX 1024
#define CPE 18                  // chunks per event
#define GRID (CPE * BB)         // 144 blocks, all resident in wave 1
#define NTHR 512
#define PB_CH 14564             // ceil(NN/CPE), divisible by 4
#define RCH 64                  // rep j-chunk size (16 chunks x 8 events = 128 blocks)

// ---------------- scratch (device globals; zero == reset state) ----------------
__device__ float  g_sum_f [BB][KK];
__device__ int    g_cnt_cp[BB][KK];
__device__ int    g_inst  [BB][KK];
__device__ int    g_first [BB][KK];   // stores max(NN - li); 0 == no CP
__device__ float  g_sd2   [BB][KK];
__device__ int    g_Mv    [BB];
__device__ int    g_cplist[BB][CAP];
__device__ float  g_scal_f[BB][4];
__device__ int    g_scal_i[BB][2];    // 0: n_cp(all), 1: n_bg
__device__ float  g_rep   [BB];

// grid barrier state (gen grows monotonically across replays -> replay-safe)
__device__ unsigned          g_bar_cnt[2];
__device__ volatile unsigned g_bar_gen[2];

__device__ __forceinline__ void grid_barrier(int idx) {
    __syncthreads();
    if (threadIdx.x == 0) {
        __threadfence();
        const unsigned my = g_bar_gen[idx];
        const unsigned arr = atomicAdd(&g_bar_cnt[idx], 1u);
        if (arr == GRID - 1) {
            g_bar_cnt[idx] = 0;
            __threadfence();
            g_bar_gen[idx] = my + 1;
        } else {
            while (g_bar_gen[idx] == my) { }
        }
        __threadfence();
    }
    __syncthreads();
}

// fast sigmoid + softplus: 2 MUFU + FMA-pipe Newton rcp (seed valid on u in (1,2])
__device__ __forceinline__ void fast_sig_sp(float x, float& p, float& ce0) {
    const float t = __expf(-fabsf(x));
    const float u = 1.f + t;
    float y = __fmaf_rn(u, -0.47058824f, 1.4117647f);
    y = y * __fmaf_rn(-u, y, 2.f);
    y = y * __fmaf_rn(-u, y, 2.f);
    ce0 = fmaxf(x, 0.f) + __logf(u);
    p   = (x >= 0.f) ? y : t * y;
}

__global__ void __launch_bounds__(NTHR) fused_all_kernel(
    const float* __restrict__ beta,
    const float* __restrict__ embed,
    const int* __restrict__ sid,
    const int* __restrict__ cp,
    float* __restrict__ out)
{
    const int blk = blockIdx.x;
    const int tid = threadIdx.x;
    const int b     = blk / CPE;
    const int chunk = blk % CPE;
    const size_t ev_base = (size_t)b * NN;
    const int start = chunk * PB_CH;
    const int end   = min(start + PB_CH, NN);

    __shared__ float s_f[KK];
    __shared__ int   s_cnt[KK];
    __shared__ int   s_first[KK];
    __shared__ float s_sc[4];
    __shared__ int   s_si[2];
    __shared__ float4             sA[KK][4];      // 16 KB (phase 2)
    __shared__ unsigned long long spack[KK];      // 2 KB  (phase 2)
    __shared__ unsigned char      shc[KK];
    __shared__ int   sidx[CAP];                   // 8 KB  (phase 3)
    __shared__ float sj[RCH * DD];                // 4 KB  (phase 3)
    __shared__ float red[16];

    // ================= PHASE 1: pass_a =================
    if (tid < KK) { s_f[tid] = 0.f; s_cnt[tid] = 0; s_first[tid] = 0; }
    if (tid < 4) s_sc[tid] = 0.f;
    if (tid < 2) s_si[tid] = 0;
    __syncthreads();

    {
        float ce0n = 0.f, bg = 0.f, pm = 0.f, nm = 0.f;
        int ncp = 0, nbg = 0;

        for (int base = start + tid * 4; base < end; base += NTHR * 4) {
            const int4   s4 = *reinterpret_cast<const int4*>(sid + ev_base + base);
            const int4   c4 = *reinterpret_cast<const int4*>(cp  + ev_base + base);
            const float4 x4 = *reinterpret_cast<const float4*>(beta + ev_base + base);

            const int   sv[4] = {s4.x, s4.y, s4.z, s4.w};
            const int   cv[4] = {c4.x, c4.y, c4.z, c4.w};
            const float xv[4] = {x4.x, x4.y, x4.z, x4.w};

            #pragma unroll
            for (int j = 0; j < 4; j++) {
                const int   s = sv[j];
                const float x = xv[j];
                float p, ce0;
                fast_sig_sp(x, p, ce0);

                if (cv[j]) {
                    ncp++;
                    pm += fmaxf(0.8f - p, 0.f);
                    if (s >= 0) {
                        const float om = 1.f - p;
                        atomicAdd(&s_f[s], 0.75f * om * om * (ce0 - x));
                        atomicAdd(&s_cnt[s], 1);
                        atomicMax(&s_first[s], NN - (base + j));
                        int pos = atomicAdd(&g_Mv[b], 1);
                        if (pos < CAP) g_cplist[b][pos] = base + j;
                    }
                } else {
                    ce0n += ce0;
                    nm += fmaxf(p - 0.2f, 0.f);
                }
                if (s == -1) { nbg++; bg += ce0; }
            }
        }

        atomicAdd(&s_sc[0], ce0n);
        atomicAdd(&s_sc[1], bg);
        atomicAdd(&s_sc[2], pm);
        atomicAdd(&s_sc[3], nm);
        atomicAdd(&s_si[0], ncp);
        atomicAdd(&s_si[1], nbg);
    }
    __syncthreads();

    if (tid < KK) {
        if (s_f[tid] != 0.f) atomicAdd(&g_sum_f[b][tid], s_f[tid]);
        if (s_cnt[tid])      atomicAdd(&g_cnt_cp[b][tid], s_cnt[tid]);
        if (s_first[tid])    atomicMax(&g_first[b][tid], s_first[tid]);
    }
    if (tid < 4) atomicAdd(&g_scal_f[b][tid], s_sc[tid]);
    if (tid < 2) atomicAdd(&g_scal_i[b][tid], s_si[tid]);

    grid_barrier(0);

    // ================= PHASE 2: pass_b =================
    if (tid < KK) {
        spack[tid] = 0ull;
        shc[tid] = (__ldcg(&g_cnt_cp[b][tid]) > 0) ? 1 : 0;
    }
    #pragma unroll
    for (int i = tid; i < KK * 4; i += NTHR) {
        const int k = i >> 2, q = i & 3;
        const int val = __ldcg(&g_first[b][k]);
        float4 v = make_float4(0.f, 0.f, 0.f, 0.f);
        if (val > 0)
            v = reinterpret_cast<const float4*>(embed + (ev_base + (NN - val)) * DD)[q];
        sA[k][q] = v;
    }
    __syncthreads();

    #pragma unroll 2
    for (int row = start + tid; row < end; row += NTHR) {
        const int s = sid[ev_base + row];
        if (s >= 0 && shc[s]) {
            const float4* e = reinterpret_cast<const float4*>(embed + (ev_base + row) * DD);
            const float4 e0 = e[0], e1 = e[1], e2 = e[2], e3 = e[3];
            const float4 a0 = sA[s][0], a1 = sA[s][1], a2 = sA[s][2], a3 = sA[s][3];
            float d2 = 0.f;
            d2 = __fmaf_rn(e0.x - a0.x, e0.x - a0.x, d2);
            d2 = __fmaf_rn(e0.y - a0.y, e0.y - a0.y, d2);
            d2 = __fmaf_rn(e0.z - a0.z, e0.z - a0.z, d2);
            d2 = __fmaf_rn(e0.w - a0.w, e0.w - a0.w, d2);
            d2 = __fmaf_rn(e1.x - a1.x, e1.x - a1.x, d2);
            d2 = __fmaf_rn(e1.y - a1.y, e1.y - a1.y, d2);
            d2 = __fmaf_rn(e1.z - a1.z, e1.z - a1.z, d2);
            d2 = __fmaf_rn(e1.w - a1.w, e1.w - a1.w, d2);
            d2 = __fmaf_rn(e2.x - a2.x, e2.x - a2.x, d2);
            d2 = __fmaf_rn(e2.y - a2.y, e2.y - a2.y, d2);
            d2 = __fmaf_rn(e2.z - a2.z, e2.z - a2.z, d2);
            d2 = __fmaf_rn(e2.w - a2.w, e2.w - a2.w, d2);
            d2 = __fmaf_rn(e3.x - a3.x, e3.x - a3.x, d2);
            d2 = __fmaf_rn(e3.y - a3.y, e3.y - a3.y, d2);
            d2 = __fmaf_rn(e3.z - a3.z, e3.z - a3.z, d2);
            d2 = __fmaf_rn(e3.w - a3.w, e3.w - a3.w, d2);
            atomicAdd(&spack[s], (1ull << 44) + __float2ull_rn(d2 * 1048576.f));
        }
    }
    __syncthreads();
    if (tid < KK) {
        const unsigned long long v = spack[tid];
        if (v) {
            atomicAdd(&g_inst[b][tid], (int)(v >> 44));
            const float ds = (float)(v & ((1ull << 44) - 1ull)) * (1.f / 1048576.f);
            if (ds != 0.f) atomicAdd(&g_sd2[b][tid], ds);
        }
    }

    // ================= PHASE 3: repulsion (blocks 0..127) =================
    if (blk < 128) {
        const int rb = blk >> 4;                 // event
        const int j0 = (blk & 15) * RCH;
        const int Mv   = __ldcg(&g_Mv[rb]);
        const int msel = min(Mv, MMAX);
        if (j0 < msel) {
            const int cnt = min(RCH, msel - j0);
            const int mcol = min(Mv, CAP);
            for (int i = tid; i < CAP; i += NTHR)
                sidx[i] = (i < mcol) ? __ldcg(&g_cplist[rb][i]) : 0x7fffffff;
            __syncthreads();

            if (Mv > MMAX) {   // statistically never; correctness fallback
                for (int ksz = 2; ksz <= CAP; ksz <<= 1) {
                    for (int j = ksz >> 1; j > 0; j >>= 1) {
                        for (int i = tid; i < CAP; i += NTHR) {
                            int ixj = i ^ j;
                            if (ixj > i) {
                                bool up = ((i & ksz) == 0);
                                int a = sidx[i], c = sidx[ixj];
                                if ((a > c) == up) { sidx[i] = c; sidx[ixj] = a; }
                            }
                        }
                        __syncthreads();
                    }
                }
            }

            const size_t rev_base = (size_t)rb * NN;
            for (int t = tid; t < cnt * 4; t += NTHR) {
                const int j = t >> 2, qq = t & 3;
                reinterpret_cast<float4*>(sj)[t] =
                    reinterpret_cast<const float4*>(embed + (rev_base + sidx[j0 + j]) * DD)[qq];
            }
            __syncthreads();

            float acc = 0.f;
            for (int i = tid; i < msel; i += NTHR) {
                float myE[DD];
                const float4* er = reinterpret_cast<const float4*>(embed + (rev_base + sidx[i]) * DD);
                #pragma unroll
                for (int qq = 0; qq < 4; qq++) {
                    const float4 v = er[qq];
                    myE[qq * 4 + 0] = v.x; myE[qq * 4 + 1] = v.y;
                    myE[qq * 4 + 2] = v.z; myE[qq * 4 + 3] = v.w;
                }
                #pragma unroll 2
                for (int j = 0; j < cnt; j++) {
                    float d2 = 0.f;
                    #pragma unroll
                    for (int d = 0; d < DD; d++) {
                        const float df = myE[d] - sj[j * DD + d];
                        d2 = __fmaf_rn(df, df, d2);
                    }
                    acc += __expf(-d2);
                }
            }

            #pragma unroll
            for (int off = 16; off; off >>= 1) acc += __shfl_down_sync(0xffffffff, acc, off);
            if ((tid & 31) == 0) red[tid >> 5] = acc;
            __syncthreads();
            if (tid == 0) {
                float tot = 0.f;
                #pragma unroll
                for (int w = 0; w < 16; w++) tot += red[w];
                atomicAdd(&g_rep[rb], tot);
            }
        }
    }

    grid_barrier(1);

    // ================= PHASE 4: finalize + reset (block 0 only) =================
    if (blk == 0) {
        const int lane = tid & 31;
        const int wid  = tid >> 5;

        __shared__ float s_loss[BB];
        __shared__ int   s_ok[BB];

        if (wid < BB) {
            const int e = wid;
            int   c[8], inst[8];
            float sf[8], sd[8];
            #pragma unroll
            for (int i = 0; i < 8; i++) {
                const int k = lane + i * 32;
                c[i]    = __ldcg(&g_cnt_cp[e][k]);
                inst[i] = __ldcg(&g_inst[e][k]);
                sf[i]   = __ldcg(&g_sum_f[e][k]);
                sd[i]   = __ldcg(&g_sd2[e][k]);
            }

            float w = 0.f, wf = 0.f, at = 0.f;
            #pragma unroll
            for (int i = 0; i < 8; i++) {
                if (c[i] > 0) {
                    const float fw = (float)inst[i];
                    w  += fw;
                    wf += fw * sf[i] / fmaxf((float)c[i], 1.f);
                    at += sd[i] / fmaxf((float)inst[i], 1.f);
                }
            }
            #pragma unroll
            for (int off = 16; off; off >>= 1) {
                w  += __shfl_down_sync(0xffffffff, w,  off);
                wf += __shfl_down_sync(0xffffffff, wf, off);
                at += __shfl_down_sync(0xffffffff, at, off);
            }

            if (lane == 0) {
                const float pos_bce = wf / fmaxf(w, 1.f);

                const float n_cp  = (float)__ldcg(&g_scal_i[e][0]);
                const float n_bg  = (float)__ldcg(&g_scal_i[e][1]);
                const float n_ncp = (float)NN - n_cp;
                const float n_val = (float)NN - n_bg;

                const float f0 = __ldcg(&g_scal_f[e][0]);
                const float f1 = __ldcg(&g_scal_f[e][1]);
                const float f2 = __ldcg(&g_scal_f[e][2]);
                const float f3 = __ldcg(&g_scal_f[e][3]);

                const float neg_bce    = (n_ncp > 0.f) ? f0 / fmaxf(n_ncp, 1.f) : 0.f;
                const float bg_bce     = (n_bg  > 0.f) ? f1 / fmaxf(n_bg,  1.f) : 0.f;
                const float pos_margin = f2 / fmaxf(n_cp, 1.f);
                const float neg_margin = (n_ncp > 0.f) ? f3 / fmaxf(n_ncp, 1.f) : 0.f;

                const float beta_loss = 10.f * pos_bce + 3.f * neg_bce + 6.f * bg_bce
                                      + 10.f * (pos_margin + neg_margin);

                const int   Mv = __ldcg(&g_Mv[e]);
                const float fM = (float)Mv;
                const float rep_term = (Mv > 1) ? __ldcg(&g_rep[e]) / fmaxf(fM * fM, 1.f) : 0.f;

                s_loss[e] = beta_loss + at + rep_term;
                s_ok[e]   = (n_val > 0.f) && (Mv > 0);
            }
        }
        __syncthreads();

        if (tid == 0) {
            float total = 0.f, cnt = 0.f;
            #pragma unroll
            for (int e = 0; e < BB; e++)
                if (s_ok[e]) { total += s_loss[e]; cnt += 1.f; }
            out[0] = (cnt > 0.f) ? total / fmaxf(cnt, 1.f) : 0.f;
        }
        __syncthreads();

        // reset all scratch so the graph replays deterministically
        for (int t = tid; t < BB * KK; t += NTHR) {
            const int e = t >> 8, k = t & 255;
            g_sum_f[e][k]  = 0.f;
            g_cnt_cp[e][k] = 0;
            g_inst[e][k]   = 0;
            g_first[e][k]  = 0;
            g_sd2[e][k]    = 0.f;
        }
        if (tid < BB) {
            g_Mv[tid]  = 0;
            g_rep[tid] = 0.f;
            #pragma unroll
            for (int j = 0; j < 4; j++) g_scal_f[tid][j] = 0.f;
            g_scal_i[tid][0] = 0; g_scal_i[tid][1] = 0;
        }
    }
}

// ---------------- launch: ONE persistent kernel ----------------
extern "C" void kernel_launch(void* const* d_in, const int* in_sizes, int n_in,
                              void* d_out, int out_size)
{
    (void)in_sizes; (void)n_in; (void)out_size;
    const float* beta  = (const float*)d_in[0];
    const float* embed = (const float*)d_in[1];
    const int*   sid   = (const int*)d_in[2];
    const int*   cp    = (const int*)d_in[3];

    fused_all_kernel<<<GRID, NTHR>>>(beta, embed, sid, cp, (float*)d_out);
}